// round 7
// baseline (speedup 1.0000x reference)
#include <cuda_runtime.h>

// Fixed problem shape: B=16, C=1, H=128, W=8192, NMAX=64
#define BB   16
#define HH   128
#define WW   8192
#define NMX  64
#define ROWS_PER_BLOCK 16       // grid.z = 8
#define BIGV 0x3FFFFFFF

// Scratch for segment metadata (allocation-free rule: device globals)
__device__ int g_start[BB][NMX];
__device__ int g_end[BB][NMX];
__device__ int g_src0[BB][NMX];
__device__ int g_n[BB];

// ---------------------------------------------------------------------------
// Kernel 1: per-batch metadata. 16 blocks x 64 threads. Prefix-scan of chirp
// widths -> compressed starts/ends; writes xi_new to output tail.
// ---------------------------------------------------------------------------
__global__ void meta_kernel(const int* __restrict__ xi,
                            const int* __restrict__ N,
                            float* __restrict__ out_xi,
                            int write_xi) {
    const int b = blockIdx.x;
    const int i = threadIdx.x;            // 0..63
    __shared__ int sh_w0;

    const int n = N[b];
    const int s = xi[(b * NMX + i) * 2 + 0];
    const int e = xi[(b * NMX + i) * 2 + 1];
    const int valid = (i < n) ? 1 : 0;
    const int wv = valid ? max(e - s, 0) : 0;

    int sc = wv;
    #pragma unroll
    for (int off = 1; off < 32; off <<= 1) {
        int v = __shfl_up_sync(0xFFFFFFFFu, sc, off);
        if ((i & 31) >= off) sc += v;
    }
    if (i == 31) sh_w0 = sc;
    __syncthreads();
    const int csum = sc + ((i >= 32) ? sh_w0 : 0);
    const int sn = csum - wv + i;         // compressed start
    const int en = csum + i;              // compressed end

    g_start[b][i] = valid ? sn : BIGV;    // sentinel keeps array sorted
    g_end[b][i]   = en;
    g_src0[b][i]  = s;
    if (i == 0) g_n[b] = n;

    if (write_xi) {
        out_xi[(b * NMX + i) * 2 + 0] = valid ? (float)sn : 0.0f;
        out_xi[(b * NMX + i) * 2 + 1] = valid ? (float)en : 0.0f;
    }
}

// ---------------------------------------------------------------------------
// Kernel 2: pack/gather. grid = (8, 16, 8) = 1024 blocks, block = 256,
// __launch_bounds__(256, 8): regs capped at 32 -> 8 blocks/SM -> ONE wave.
// Each thread: 4 consecutive columns x 16 rows. One binary search per thread
// (segments are contiguous, min extent > 4, so 4 consecutive columns cross
// at most one boundary). Per-column state is a single int offset:
//   off >= 0 : gather from xb + row + off
//   off == -1: separator value
//   off == -2: zero fill
// ---------------------------------------------------------------------------
__global__ void __launch_bounds__(256, 8)
pack_kernel(const float* __restrict__ x,
            const float* __restrict__ sep_param,
            float* __restrict__ out) {
    const int b = blockIdx.y;
    const int t = threadIdx.x;

    __shared__ int   s_start[NMX + 1];   // +1 sentinel slot
    __shared__ int   s_end[NMX];
    __shared__ int   s_src[NMX];
    __shared__ int   s_n;
    __shared__ float s_sep;

    if (t < NMX) {
        s_start[t] = g_start[b][t];
        s_end[t]   = g_end[b][t];
        s_src[t]   = g_src0[b][t];
    }
    if (t == 0) { s_n = g_n[b]; s_sep = sep_param[0]; s_start[NMX] = BIGV; }
    __syncthreads();

    const int n  = s_n;
    const int j0 = (blockIdx.x * 256 + t) * 4;

    // upper_bound(start, j0) - 1 ; start[0] == 0 so seg >= 0 always
    int lo = 0, hi = n;
    while (lo < hi) {
        int mid = (lo + hi) >> 1;
        if (s_start[mid] <= j0) lo = mid + 1; else hi = mid;
    }
    int cur = lo - 1;

    int off[4];
    #pragma unroll
    for (int c = 0; c < 4; c++) {
        const int j = j0 + c;
        if (j >= s_start[cur + 1]) cur++;     // at most one boundary in 4 cols
        const int s = s_start[cur];
        const int e = s_end[cur];
        int o = -2;                            // zero fill by default
        if (j < e)                 o = min(max(s_src[cur] + (j - s), 0), WW - 1);
        else if (j == e && cur < n - 1) o = -1; // separator
        off[c] = o;
    }

    const float sep = s_sep;
    const int h0 = blockIdx.z * ROWS_PER_BLOCK;
    const float* __restrict__ xb = x   + (size_t)b * HH * WW + (size_t)h0 * WW;
    float* __restrict__       ob = out + (size_t)b * HH * WW + (size_t)h0 * WW;

    #pragma unroll 4
    for (int hh = 0; hh < ROWS_PER_BLOCK; hh++) {
        const size_t row = (size_t)hh * WW;
        float4 v;
        v.x = (off[0] >= 0) ? __ldg(xb + row + off[0]) : ((off[0] == -1) ? sep : 0.0f);
        v.y = (off[1] >= 0) ? __ldg(xb + row + off[1]) : ((off[1] == -1) ? sep : 0.0f);
        v.z = (off[2] >= 0) ? __ldg(xb + row + off[2]) : ((off[2] == -1) ? sep : 0.0f);
        v.w = (off[3] >= 0) ? __ldg(xb + row + off[3]) : ((off[3] == -1) ? sep : 0.0f);
        *reinterpret_cast<float4*>(ob + row + j0) = v;
    }
}

// ---------------------------------------------------------------------------
extern "C" void kernel_launch(void* const* d_in, const int* in_sizes, int n_in,
                              void* d_out, int out_size) {
    const float* x   = (const float*)d_in[0];
    const int*   xi  = (const int*)  d_in[1];
    const int*   N   = (const int*)  d_in[2];
    const float* sep = (const float*)d_in[3];
    float*       out = (float*)d_out;

    const long long XN = (long long)BB * HH * WW;   // 16,777,216
    const int write_xi = ((long long)out_size > XN) ? 1 : 0;

    meta_kernel<<<BB, NMX>>>(xi, N, out + XN, write_xi);

    dim3 grid(WW / (256 * 4), BB, HH / ROWS_PER_BLOCK);
    pack_kernel<<<grid, 256>>>(x, sep, out);
}

// round 8
// speedup vs baseline: 1.6470x; 1.6470x over previous
#include <cuda_runtime.h>

// Fixed problem shape: B=16, C=1, H=128, W=8192, NMAX=64
#define BB   16
#define HH   128
#define WW   8192
#define NMX  64
#define ROWS_PER_BLOCK 8        // grid.z = 16 -> 2048 blocks total
#define BIGV 0x3FFFFFFF

// Scratch for segment metadata (allocation-free rule: device globals)
__device__ int g_start[BB][NMX];
__device__ int g_end[BB][NMX];
__device__ int g_src0[BB][NMX];
__device__ int g_n[BB];

// ---------------------------------------------------------------------------
// Kernel 1: per-batch metadata. 16 blocks x 64 threads. Prefix-scan of chirp
// widths -> compressed starts/ends; writes xi_new to output tail.
// ---------------------------------------------------------------------------
__global__ void meta_kernel(const int* __restrict__ xi,
                            const int* __restrict__ N,
                            float* __restrict__ out_xi,
                            int write_xi) {
    const int b = blockIdx.x;
    const int i = threadIdx.x;            // 0..63
    __shared__ int sh_w0;

    const int n = N[b];
    const int s = xi[(b * NMX + i) * 2 + 0];
    const int e = xi[(b * NMX + i) * 2 + 1];
    const int valid = (i < n) ? 1 : 0;
    const int wv = valid ? max(e - s, 0) : 0;

    int sc = wv;
    #pragma unroll
    for (int off = 1; off < 32; off <<= 1) {
        int v = __shfl_up_sync(0xFFFFFFFFu, sc, off);
        if ((i & 31) >= off) sc += v;
    }
    if (i == 31) sh_w0 = sc;
    __syncthreads();
    const int csum = sc + ((i >= 32) ? sh_w0 : 0);
    const int sn = csum - wv + i;         // compressed start
    const int en = csum + i;              // compressed end

    g_start[b][i] = valid ? sn : BIGV;    // sentinel keeps array sorted
    g_end[b][i]   = en;
    g_src0[b][i]  = s;
    if (i == 0) g_n[b] = n;

    if (write_xi) {
        out_xi[(b * NMX + i) * 2 + 0] = valid ? (float)sn : 0.0f;
        out_xi[(b * NMX + i) * 2 + 1] = valid ? (float)en : 0.0f;
    }
}

// ---------------------------------------------------------------------------
// Kernel 2: pack/gather. grid = (8, 16, 16) = 2048 blocks, block = 256.
// Each thread owns 4 consecutive columns x 8 rows. One binary search per
// thread (segments contiguous, min extent > 4 -> at most one boundary in 4
// consecutive columns). float4 streaming stores. Natural register allocation
// (NO occupancy cap -- round 7 showed capping causes spills).
// ---------------------------------------------------------------------------
__global__ void __launch_bounds__(256)
pack_kernel(const float* __restrict__ x,
            const float* __restrict__ sep_param,
            float* __restrict__ out) {
    const int b = blockIdx.y;
    const int t = threadIdx.x;

    __shared__ int   s_start[NMX + 1];   // +1 sentinel slot
    __shared__ int   s_end[NMX];
    __shared__ int   s_src[NMX];
    __shared__ int   s_n;
    __shared__ float s_sep;

    if (t < NMX) {
        s_start[t] = g_start[b][t];
        s_end[t]   = g_end[b][t];
        s_src[t]   = g_src0[b][t];
    }
    if (t == 0) { s_n = g_n[b]; s_sep = sep_param[0]; s_start[NMX] = BIGV; }
    __syncthreads();

    const int n  = s_n;
    const int j0 = (blockIdx.x * 256 + t) * 4;

    // upper_bound(start, j0) - 1 ; start[0] == 0 so seg >= 0 always
    int lo = 0, hi = n;
    while (lo < hi) {
        int mid = (lo + hi) >> 1;
        if (s_start[mid] <= j0) lo = mid + 1; else hi = mid;
    }
    int cur = lo - 1;

    bool  gth[4];
    int   src[4];
    float fil[4];
    #pragma unroll
    for (int c = 0; c < 4; c++) {
        const int j = j0 + c;
        if (j >= s_start[cur + 1]) cur++;     // at most one boundary in 4 cols
        gth[c] = false; src[c] = 0; fil[c] = 0.0f;
        const int s = s_start[cur];
        const int e = s_end[cur];
        if (j < e) {
            gth[c] = true;
            src[c] = min(max(s_src[cur] + (j - s), 0), WW - 1);
        } else if (j == e && cur < n - 1) {
            fil[c] = s_sep;
        }
    }

    const int h0 = blockIdx.z * ROWS_PER_BLOCK;
    const float* __restrict__ xb = x   + (size_t)b * HH * WW + (size_t)h0 * WW;
    float* __restrict__       ob = out + (size_t)b * HH * WW + (size_t)h0 * WW;

    #pragma unroll 4
    for (int hh = 0; hh < ROWS_PER_BLOCK; hh++) {
        const size_t row = (size_t)hh * WW;
        float4 v;
        v.x = gth[0] ? __ldg(xb + row + src[0]) : fil[0];
        v.y = gth[1] ? __ldg(xb + row + src[1]) : fil[1];
        v.z = gth[2] ? __ldg(xb + row + src[2]) : fil[2];
        v.w = gth[3] ? __ldg(xb + row + src[3]) : fil[3];
        __stcs(reinterpret_cast<float4*>(ob + row + j0), v);
    }
}

// ---------------------------------------------------------------------------
extern "C" void kernel_launch(void* const* d_in, const int* in_sizes, int n_in,
                              void* d_out, int out_size) {
    const float* x   = (const float*)d_in[0];
    const int*   xi  = (const int*)  d_in[1];
    const int*   N   = (const int*)  d_in[2];
    const float* sep = (const float*)d_in[3];
    float*       out = (float*)d_out;

    const long long XN = (long long)BB * HH * WW;   // 16,777,216
    const int write_xi = ((long long)out_size > XN) ? 1 : 0;

    meta_kernel<<<BB, NMX>>>(xi, N, out + XN, write_xi);

    dim3 grid(WW / (256 * 4), BB, HH / ROWS_PER_BLOCK);
    pack_kernel<<<grid, 256>>>(x, sep, out);
}